// round 16
// baseline (speedup 1.0000x reference)
#include <cuda_runtime.h>
#include <cstdint>

// CRF forward scan — R15 engine, TWO BATCHES PER THREAD (shared W registers).
// 256 blocks x 64 threads; block handles batches 2b, 2b+1 in lockstep.
// Thread tid owns state tid for BOTH batches. Per step & batch: packed f32x2
// partials over own warp's v-half for columns tid (kept) and tid^32
// (published as one u64). ONE __syncthreads per step serves both batches.
// Shift m = stale-by-1 alpha[1] per batch. alpha base-2 scaled; ex2/lg2
// approx PTX. feats/masks staged via cp.async 3-buffer pipeline.

#define TT 64
#define CHUNK 16
#define L2E 1.4426950408889634f
#define LN2 0.6931471805599453f
typedef unsigned long long u64;

__device__ float g_Wt[TT * TT];  // g_Wt[j*64+i] = exp(trans[i][j]-c_j)
__device__ float g_c2[TT];       // c_j * log2(e)

__device__ __forceinline__ void unpack2(u64 v, float& lo, float& hi) {
    asm("mov.b64 {%0, %1}, %2;" : "=f"(lo), "=f"(hi) : "l"(v));
}
__device__ __forceinline__ u64 ffma2(u64 a, u64 b, u64 c) {
    u64 d; asm("fma.rn.f32x2 %0, %1, %2, %3;" : "=l"(d) : "l"(a), "l"(b), "l"(c)); return d;
}
__device__ __forceinline__ u64 fadd2(u64 a, u64 b) {
    u64 d; asm("add.rn.f32x2 %0, %1, %2;" : "=l"(d) : "l"(a), "l"(b)); return d;
}
__device__ __forceinline__ float ex2f(float x) {
    float y; asm("ex2.approx.f32 %0, %1;" : "=f"(y) : "f"(x)); return y;
}
__device__ __forceinline__ float lg2f(float x) {
    float y; asm("lg2.approx.f32 %0, %1;" : "=f"(y) : "f"(x)); return y;
}
__device__ __forceinline__ uint32_t smem_u32(const void* p) {
    uint32_t a;
    asm("{ .reg .u64 t; cvta.to.shared.u64 t, %1; cvt.u32.u64 %0, t; }" : "=r"(a) : "l"(p));
    return a;
}

// ---------------------------------------------------------------------------
__global__ void crf_prep_kernel(const float* __restrict__ trans) {
    int j = threadIdx.x;
    float c = -3.402823466e+38f;
    #pragma unroll
    for (int i = 0; i < TT; i++) c = fmaxf(c, trans[i * TT + j]);
    g_c2[j] = c * L2E;
    #pragma unroll
    for (int i = 0; i < TT; i++) g_Wt[j * TT + i] = __expf(trans[i * TT + j] - c);
}

// ---------------------------------------------------------------------------
__global__ void __launch_bounds__(64) crf_scan_kernel(
    const float* __restrict__ feats,   // [B, S, 64]
    const float* __restrict__ masks,   // [B, S]
    float* __restrict__ out,           // [B, 64]
    int Sdim, int Bn)
{
    const int tid = threadIdx.x;
    const int w2  = tid >> 5;
    const int b0  = blockIdx.x * 2;
    const int b1  = (b0 + 1 < Bn) ? (b0 + 1) : b0;

    __shared__ alignas(16) float s_feat[2][3][CHUNK][TT];  // 24 KB
    __shared__ float s_mask[2][3][CHUNK];
    __shared__ alignas(16) float s_v[2][TT];               // per-batch v (BAR-ordered)
    __shared__ u64 s_part[2][2][TT];                       // [batch][buf][state]
    __shared__ float s_mring[2][2];                        // per-batch alpha[1] ring

    // Shared W: columns tid (own) and tid^32, rows [32*w2, 32*w2+32).
    u64 wA[16], wB[16];
    {
        const ulonglong2* pa =
            reinterpret_cast<const ulonglong2*>(&g_Wt[tid * TT + 32 * w2]);
        const ulonglong2* pb =
            reinterpret_cast<const ulonglong2*>(&g_Wt[(tid ^ 32) * TT + 32 * w2]);
        #pragma unroll
        for (int q = 0; q < 8; q++) {
            ulonglong2 ua = pa[q];
            wA[2 * q]     = ua.x;
            wA[2 * q + 1] = ua.y;
            ulonglong2 ub = pb[q];
            wB[2 * q]     = ub.x;
            wB[2 * q + 1] = ub.y;
        }
    }
    const float cj2 = g_c2[tid];

    const float* fb0 = feats + (size_t)b0 * Sdim * TT;
    const float* fb1 = feats + (size_t)b1 * Sdim * TT;
    const float* mb0 = masks + (size_t)b0 * Sdim;
    const float* mb1 = masks + (size_t)b1 * Sdim;
    const uint32_t feat_s0 = smem_u32(&s_feat[0][0][0][0]);
    const uint32_t feat_s1 = smem_u32(&s_feat[1][0][0][0]);
    const uint32_t mask_s0 = smem_u32(&s_mask[0][0][0]);
    const uint32_t mask_s1 = smem_u32(&s_mask[1][0][0]);

    const int NC   = (Sdim + CHUNK - 1) / CHUNK;
    const int tail = Sdim - (NC - 1) * CHUNK;

    auto stage = [&](int c) {
        const int base = c * CHUNK;
        const int bufo = (c % 3) * CHUNK * TT;
        #pragma unroll
        for (int q = 0; q < 4; q++) {
            int g   = q * 64 + tid;        // 16B granule 0..255
            int row = g >> 4;
            int col = (g & 15) << 2;
            int gr  = base + row; if (gr >= Sdim) gr = Sdim - 1;
            uint32_t off = (uint32_t)(bufo + row * TT + col) * 4u;
            const float* s0 = fb0 + (size_t)gr * TT + col;
            const float* s1 = fb1 + (size_t)gr * TT + col;
            asm volatile("cp.async.cg.shared.global [%0], [%1], 16;" :: "r"(feat_s0 + off), "l"(s0));
            asm volatile("cp.async.cg.shared.global [%0], [%1], 16;" :: "r"(feat_s1 + off), "l"(s1));
        }
        if (tid < CHUNK) {
            int gr = base + tid; if (gr >= Sdim) gr = Sdim - 1;
            uint32_t off = (uint32_t)((c % 3) * CHUNK + tid) * 4u;
            const float* s0 = mb0 + gr;
            const float* s1 = mb1 + gr;
            asm volatile("cp.async.ca.shared.global [%0], [%1], 4;" :: "r"(mask_s0 + off), "l"(s0));
            asm volatile("cp.async.ca.shared.global [%0], [%1], 4;" :: "r"(mask_s1 + off), "l"(s1));
        }
    };

    stage(0);
    asm volatile("cp.async.commit_group;");
    if (NC > 1) stage(1);
    asm volatile("cp.async.commit_group;");
    asm volatile("cp.async.wait_group 1;");
    __syncthreads();

    float aX = s_feat[0][0][0][tid] * L2E;   // base-2 scaled alpha0, batch b0
    float aY = s_feat[1][0][0][tid] * L2E;   // batch b1

    if (tid == 1) { s_mring[0][1] = aX; s_mring[1][1] = aY; }
    __syncthreads();
    float mX = s_mring[0][1];
    float mY = s_mring[1][1];

    // One double-step (both batches). r is compile-time constant when unrolled.
    auto step = [&](int c3, int r) {
        // Chain heads: exp2 with stale shift, publish v for both batches.
        const float vX = ex2f(aX - mX);
        const float vY = ex2f(aY - mY);
        s_v[0][tid] = vX;
        s_v[1][tid] = vY;

        if (tid == 1) {
            s_mring[0][(r & 1) ^ 1] = aX;
            s_mring[1][(r & 1) ^ 1] = aY;
        }

        // Off-chain: staged feats/masks, pre-activations.
        const float ftX  = s_feat[0][c3][r][tid];
        const float ftY  = s_feat[1][c3][r][tid];
        const float mkX  = s_mask[0][c3][r];
        const float mkY  = s_mask[1][c3][r];
        const float preX = fmaf(ftX, L2E, cj2 + mX);
        const float preY = fmaf(ftY, L2E, cj2 + mY);

        __syncwarp();

        // Interleaved matvecs, both batches, shared W (2 accs per column).
        const ulonglong2* vpX = reinterpret_cast<const ulonglong2*>(&s_v[0][32 * w2]);
        const ulonglong2* vpY = reinterpret_cast<const ulonglong2*>(&s_v[1][32 * w2]);
        u64 xa0 = 0ull, xa1 = 0ull, xb0 = 0ull, xb1 = 0ull;
        u64 ya0 = 0ull, ya1 = 0ull, yb0 = 0ull, yb1 = 0ull;
        #pragma unroll
        for (int q = 0; q < 8; q++) {
            ulonglong2 ux = vpX[q];
            xa0 = ffma2(ux.x, wA[2 * q],     xa0);
            xa1 = ffma2(ux.y, wA[2 * q + 1], xa1);
            xb0 = ffma2(ux.x, wB[2 * q],     xb0);
            xb1 = ffma2(ux.y, wB[2 * q + 1], xb1);
            ulonglong2 uy = vpY[q];
            ya0 = ffma2(uy.x, wA[2 * q],     ya0);
            ya1 = ffma2(uy.y, wA[2 * q + 1], ya1);
            yb0 = ffma2(uy.x, wB[2 * q],     yb0);
            yb1 = ffma2(uy.y, wB[2 * q + 1], yb1);
        }
        const u64 sXA = fadd2(xa0, xa1);
        const u64 sXB = fadd2(xb0, xb1);
        const u64 sYA = fadd2(ya0, ya1);
        const u64 sYB = fadd2(yb0, yb1);

        s_part[0][r & 1][tid ^ 32] = sXB;
        s_part[1][r & 1][tid ^ 32] = sYB;

        __syncthreads();                    // the ONLY block barrier

        const u64 cX = fadd2(sXA, s_part[0][r & 1][tid]);
        const u64 cY = fadd2(sYA, s_part[1][r & 1][tid]);
        float xl, xh, yl, yh;
        unpack2(cX, xl, xh);
        unpack2(cY, yl, yh);
        const float PX = xl + xh;
        const float PY = yl + yh;
        const float nX = preX + lg2f(PX);
        const float nY = preY + lg2f(PY);
        aX = (mkX != 0.0f) ? nX : aX;
        aY = (mkY != 0.0f) ? nY : aY;
        mX = s_mring[0][(r & 1) ^ 1];
        mY = s_mring[1][(r & 1) ^ 1];
    };

    for (int c = 0; c < NC; c++) {
        if (c > 0) asm volatile("cp.async.wait_group 1;");
        if (c + 2 < NC) stage(c + 2);
        asm volatile("cp.async.commit_group;");
        __syncthreads();

        const int c3 = c % 3;
        if (c + 1 < NC) {
            #pragma unroll
            for (int r = 0; r < CHUNK; r++) {
                if (r == 0 && c == 0) continue;    // skip t = 0 only
                step(c3, r);
            }
        } else {
            for (int r = 0; r < tail; r++) {
                if (r == 0 && c == 0) continue;
                step(c3, r);
            }
        }
    }

    out[(size_t)b0 * TT + tid] = aX * LN2;
    if (b1 != b0) out[(size_t)b1 * TT + tid] = aY * LN2;
}

// ---------------------------------------------------------------------------
extern "C" void kernel_launch(void* const* d_in, const int* in_sizes, int n_in,
                              void* d_out, int out_size) {
    const float* feats = (const float*)d_in[0];
    const float* masks = (const float*)d_in[1];
    const float* trans = (const float*)d_in[2];
    float* out = (float*)d_out;

    const int Bn   = out_size / TT;
    const int Sdim = in_sizes[0] / (Bn * TT);

    crf_prep_kernel<<<1, TT>>>(trans);
    crf_scan_kernel<<<(Bn + 1) / 2, TT>>>(feats, masks, out, Sdim, Bn);
}